// round 10
// baseline (speedup 1.0000x reference)
#include <cuda_runtime.h>

// out[r][c] = posenc(X[r]) . W[3*voxel_ids[p] + c],  r = row_ids[p]
//
//  K0 repack: g_Wp[v*96 + c*32 + a] = (w_sin, w_cos) for angle a=3f+d (a<30);
//             a=30: (raw w_d0, raw w_d1); a=31: (raw w_d2, 0)
//  K1 rank:   pos[p] = atomicAdd(cnt[voxel_ids[p]], 1)   (int4-vectorized)
//  K2 scan:   padded-to-32 exclusive scan -> g_ps; self-resets counters
//  K3 scatter+pad: g_pts[g_ps[v]+pos] = float4(x, v<<18|r); pad slots marked bit31
//  K4 flat:   grid-stride, 1 slot/thread; every warp inside one bin (32-padding)
//             -> warp-uniform voxel, broadcast LDG.64 weights from L1; no smem,
//             no syncthreads, no per-CTA bin mapping. Single wave (888 CTAs).

#define NUM_VOXELS 512
#define PAD 32                         // counter stride in ints = 128 B
#define NPTS_MAX (1 << 18)
#define NSLOT_MAX (NPTS_MAX + NUM_VOXELS * 31 + 32)
#define K4_BLOCKS 888                  // 148 SMs * 6 CTAs -> one wave at 42 regs

__device__ int    g_cnt[NUM_VOXELS * PAD];    // zero-init; self-reset by K2
__device__ int    g_rcnt[NUM_VOXELS];         // real (unpadded) counts
__device__ int    g_pos[NPTS_MAX];
__device__ int    g_ps[NUM_VOXELS + 1];       // padded exclusive scan
__device__ float4 g_pts[NSLOT_MAX];
__device__ float2 g_Wp[NUM_VOXELS * 96];      // repacked weights

// ---- K0: repack W into (sin,cos)-paired float2 table ----
__global__ void __launch_bounds__(256)
repack_kernel(const float* __restrict__ W)
{
    int idx = blockIdx.x * 256 + threadIdx.x;     // 512*96 float2
    if (idx >= NUM_VOXELS * 96) return;
    int v = idx / 96;
    int t = idx - v * 96;
    int c = t >> 5;            // channel 0..2
    int a = t & 31;            // angle slot
    const float* row = W + (3 * v + c) * 63;
    float2 o;
    if (a < 30) {
        int f = a / 3, d = a - 3 * f;
        o = make_float2(row[3 + 6 * f + d], row[3 + 6 * f + 3 + d]);
    } else if (a == 30) {
        o = make_float2(row[0], row[1]);
    } else {
        o = make_float2(row[2], 0.0f);
    }
    g_Wp[idx] = o;
}

// ---- K1: per-point rank within its voxel (4 points/thread) ----
__global__ void __launch_bounds__(256)
rank_kernel(const int* __restrict__ voxel_ids, int n)
{
    int i4 = blockIdx.x * 256 + threadIdx.x;
    int p = i4 * 4;
    if (p + 3 < n) {
        int4 v4 = *reinterpret_cast<const int4*>(voxel_ids + p);
        int4 o;
        o.x = atomicAdd(&g_cnt[v4.x * PAD], 1);
        o.y = atomicAdd(&g_cnt[v4.y * PAD], 1);
        o.z = atomicAdd(&g_cnt[v4.z * PAD], 1);
        o.w = atomicAdd(&g_cnt[v4.w * PAD], 1);
        *reinterpret_cast<int4*>(g_pos + p) = o;
    } else {
        for (int q = p; q < n; ++q)
            g_pos[q] = atomicAdd(&g_cnt[voxel_ids[q] * PAD], 1);
    }
}

// ---- K2: padded scan, self-reset counters ----
__global__ void __launch_bounds__(NUM_VOXELS)
scan_kernel()
{
    __shared__ int sh[NUM_VOXELS];
    const int t = threadIdx.x;
    const int val = g_cnt[t * PAD];
    g_cnt[t * PAD] = 0;
    g_rcnt[t] = val;
    const int pval = (val + 31) & ~31;    // pad to warp multiple
    sh[t] = pval;
    __syncthreads();
#pragma unroll
    for (int off = 1; off < NUM_VOXELS; off <<= 1) {
        int x = sh[t];
        if (t >= off) x += sh[t - off];
        __syncthreads();
        sh[t] = x;
        __syncthreads();
    }
    g_ps[t] = sh[t] - pval;               // exclusive
    if (t == NUM_VOXELS - 1) g_ps[NUM_VOXELS] = sh[t];
}

// ---- K3: scatter payload + write pad markers ----
__global__ void __launch_bounds__(256)
scatter_kernel(const float* __restrict__ X,
               const int* __restrict__ row_ids,
               const int* __restrict__ voxel_ids,
               int n, int nb)
{
    const int b = blockIdx.x;
    if (b < nb) {
        int p = b * 256 + threadIdx.x;
        if (p >= n) return;
        const int v = voxel_ids[p];
        const int dst = g_ps[v] + g_pos[p];
        const int r = row_ids[p];
        float4 pay;
        pay.x = X[3 * r + 0];
        pay.y = X[3 * r + 1];
        pay.z = X[3 * r + 2];
        pay.w = __int_as_float((v << 18) | r);
        g_pts[dst] = pay;
    } else {
        const int v = b - nb;                 // pad block per voxel
        const int base = g_ps[v];
        const int cnt  = g_rcnt[v];
        const int psz  = g_ps[v + 1] - base;
        const float4 mark = make_float4(0.0f, 0.0f, 0.0f,
                                        __int_as_float((int)0x80000000u));
        for (int j = cnt + threadIdx.x; j < psz; j += 256)
            g_pts[base + j] = mark;
    }
}

// ---- K4: flat main — warp-uniform voxel, broadcast weight loads ----
__global__ void __launch_bounds__(256, 6)
voxel_main_kernel(float* __restrict__ out)
{
    const int padn = g_ps[NUM_VOXELS];
    for (int slot = blockIdx.x * 256 + threadIdx.x; slot < padn;
         slot += K4_BLOCKS * 256) {
        const float4 pay = g_pts[slot];
        const int rv = __float_as_int(pay.w);
        const int v  = (rv >> 18) & 511;      // pad slots: v=0 (harmless)
        const float x0 = pay.x, x1 = pay.y, x2 = pay.z;

        const float2* __restrict__ wp = g_Wp + v * 96;

        const float2 p0 = wp[30], p1 = wp[31];
        const float2 q0 = wp[62], q1 = wp[63];
        const float2 u0 = wp[94], u1 = wp[95];
        float a0 = x0 * p0.x; a0 = fmaf(x1, p0.y, a0); a0 = fmaf(x2, p1.x, a0);
        float a1 = x0 * q0.x; a1 = fmaf(x1, q0.y, a1); a1 = fmaf(x2, q1.x, a1);
        float a2 = x0 * u0.x; a2 = fmaf(x1, u0.y, a2); a2 = fmaf(x2, u1.x, a2);

#pragma unroll 2
        for (int f = 0; f < 10; ++f) {
            const float sc = (float)(1 << f);
#pragma unroll
            for (int d = 0; d < 3; ++d) {
                const float xv = (d == 0) ? x0 : ((d == 1) ? x1 : x2);
                float s, c;
                __sincosf(xv * sc, &s, &c);
                const int a = 3 * f + d;
                const float2 w0 = wp[a];
                a0 = fmaf(s, w0.x, a0); a0 = fmaf(c, w0.y, a0);
                const float2 w1 = wp[32 + a];
                a1 = fmaf(s, w1.x, a1); a1 = fmaf(c, w1.y, a1);
                const float2 w2 = wp[64 + a];
                a2 = fmaf(s, w2.x, a2); a2 = fmaf(c, w2.y, a2);
            }
        }

        if (rv >= 0) {                        // skip pad slots
            const int r = rv & 0x3FFFF;
            out[3 * r + 0] = a0;
            out[3 * r + 1] = a1;
            out[3 * r + 2] = a2;
        }
    }
}

extern "C" void kernel_launch(void* const* d_in, const int* in_sizes, int n_in,
                              void* d_out, int out_size)
{
    const float* X         = (const float*)d_in[0];
    const float* W         = (const float*)d_in[1];
    const int*   row_ids   = (const int*)d_in[2];
    const int*   voxel_ids = (const int*)d_in[3];
    float*       out       = (float*)d_out;

    const int n  = in_sizes[0] / 3;              // N_POINTS
    const int nb = (n + 255) / 256;

    repack_kernel<<<(NUM_VOXELS * 96 + 255) / 256, 256>>>(W);
    rank_kernel<<<((n + 3) / 4 + 255) / 256, 256>>>(voxel_ids, n);
    scan_kernel<<<1, NUM_VOXELS>>>();
    scatter_kernel<<<nb + NUM_VOXELS, 256>>>(X, row_ids, voxel_ids, n, nb);
    voxel_main_kernel<<<K4_BLOCKS, 256>>>(out);
}

// round 11
// speedup vs baseline: 1.1488x; 1.1488x over previous
#include <cuda_runtime.h>

// out[r][c] = posenc(X[r]) . W[3*voxel_ids[p] + c],  r = row_ids[p]
//
//  K1 hist:    REDG histogram of voxel ids (no return value), int4-vectorized
//  K2 scan:    exclusive scan -> g_binstart; cursors g_cur = start; cnt reset
//  K3 scatter: dst = atomicAdd(cur[v]) ; g_pts[dst] = float4(x0,x1,x2,bits(r))
//  K4 main:    2 CTAs per voxel, weights (sin,cos)-paired in smem; base
//              __sincosf at f=0 + double-angle recurrence for f=1..9
//              (MUFU/point: 60 -> 6). Reg-capped (256,6).

#define NUM_VOXELS 512
#define NPTS_MAX (1 << 18)
#define PAD 32                    // counter stride in ints = 128 B

__device__ int    g_cnt[NUM_VOXELS * PAD];   // zero-init; self-reset by K2
__device__ int    g_cur[NUM_VOXELS * PAD];   // scatter cursors
__device__ int    g_binstart[NUM_VOXELS + 1];
__device__ float4 g_pts[NPTS_MAX];

// ---- K1: histogram (atomicAdd w/o return -> REDG) ----
__global__ void __launch_bounds__(256)
hist_kernel(const int* __restrict__ voxel_ids, int n)
{
    int i4 = blockIdx.x * 256 + threadIdx.x;
    int p = i4 * 4;
    if (p + 3 < n) {
        int4 v4 = *reinterpret_cast<const int4*>(voxel_ids + p);
        atomicAdd(&g_cnt[v4.x * PAD], 1);
        atomicAdd(&g_cnt[v4.y * PAD], 1);
        atomicAdd(&g_cnt[v4.z * PAD], 1);
        atomicAdd(&g_cnt[v4.w * PAD], 1);
    } else {
        for (int q = p; q < n; ++q)
            atomicAdd(&g_cnt[voxel_ids[q] * PAD], 1);
    }
}

// ---- K2: scan counts -> binstart; init cursors; self-reset counters ----
__global__ void __launch_bounds__(NUM_VOXELS)
scan_kernel(int n)
{
    __shared__ int sh[NUM_VOXELS];
    const int t = threadIdx.x;
    const int val = g_cnt[t * PAD];
    g_cnt[t * PAD] = 0;                  // reset for next graph replay
    sh[t] = val;
    __syncthreads();
#pragma unroll
    for (int off = 1; off < NUM_VOXELS; off <<= 1) {
        int x = sh[t];
        if (t >= off) x += sh[t - off];
        __syncthreads();
        sh[t] = x;
        __syncthreads();
    }
    const int start = sh[t] - val;       // exclusive
    g_binstart[t] = start;
    g_cur[t * PAD] = start;
    if (t == NUM_VOXELS - 1) g_binstart[NUM_VOXELS] = n;
}

// ---- K3: scatter payload (rank fused via cursor atomics) ----
__global__ void __launch_bounds__(256)
scatter_kernel(const float* __restrict__ X,
               const int* __restrict__ row_ids,
               const int* __restrict__ voxel_ids,
               int n)
{
    int p = blockIdx.x * 256 + threadIdx.x;
    if (p >= n) return;
    const int v = voxel_ids[p];
    const int dst = atomicAdd(&g_cur[v * PAD], 1);
    const int r = row_ids[p];
    float4 pay;
    pay.x = X[3 * r + 0];
    pay.y = X[3 * r + 1];
    pay.z = X[3 * r + 2];
    pay.w = __int_as_float(r);
    g_pts[dst] = pay;
}

// ---- K4: main — 2 CTAs per voxel, double-angle sincos, reg-capped ----
__global__ void __launch_bounds__(256, 6)
voxel_main_kernel(const float* __restrict__ W,
                  float* __restrict__ out)
{
    __shared__ float2 Wp[3][32];     // (sin,cos) weight pairs per angle a=3f+d
    __shared__ float  Wraw[3][4];    // raw x weights
    const int v    = blockIdx.x >> 1;
    const int half = blockIdx.x & 1;
    const int t = threadIdx.x;

    if (t < 90) {
        const int c = t / 30, a = t - 30 * c;
        const int f = a / 3, d = a - 3 * f;
        const float* row = W + (3 * v + c) * 63;
        Wp[c][a] = make_float2(row[3 + 6 * f + d], row[3 + 6 * f + 3 + d]);
    } else if (t < 99) {
        const int u = t - 90;
        const int c = u / 3, d = u - 3 * c;
        Wraw[c][d] = W[(3 * v + c) * 63 + d];
    }
    __syncthreads();

    const int start = g_binstart[v];
    const int cnt   = g_binstart[v + 1] - start;

    for (int i = half * 256 + t; i < cnt; i += 512) {
        const float4 pay = g_pts[start + i];
        const float x0 = pay.x, x1 = pay.y, x2 = pay.z;
        const int   r  = __float_as_int(pay.w);

        float a0 = x0 * Wraw[0][0];
        a0 = fmaf(x1, Wraw[0][1], a0); a0 = fmaf(x2, Wraw[0][2], a0);
        float a1 = x0 * Wraw[1][0];
        a1 = fmaf(x1, Wraw[1][1], a1); a1 = fmaf(x2, Wraw[1][2], a1);
        float a2 = x0 * Wraw[2][0];
        a2 = fmaf(x1, Wraw[2][1], a2); a2 = fmaf(x2, Wraw[2][2], a2);

        // base angles (f=0)
        float s0, c0, s1, c1, s2, c2;
        __sincosf(x0, &s0, &c0);
        __sincosf(x1, &s1, &c1);
        __sincosf(x2, &s2, &c2);

#pragma unroll 2
        for (int f = 0; f < 10; ++f) {
            const int a = 3 * f;
            const float2 w00 = Wp[0][a + 0], w01 = Wp[0][a + 1], w02 = Wp[0][a + 2];
            a0 = fmaf(s0, w00.x, a0); a0 = fmaf(c0, w00.y, a0);
            a0 = fmaf(s1, w01.x, a0); a0 = fmaf(c1, w01.y, a0);
            a0 = fmaf(s2, w02.x, a0); a0 = fmaf(c2, w02.y, a0);
            const float2 w10 = Wp[1][a + 0], w11 = Wp[1][a + 1], w12 = Wp[1][a + 2];
            a1 = fmaf(s0, w10.x, a1); a1 = fmaf(c0, w10.y, a1);
            a1 = fmaf(s1, w11.x, a1); a1 = fmaf(c1, w11.y, a1);
            a1 = fmaf(s2, w12.x, a1); a1 = fmaf(c2, w12.y, a1);
            const float2 w20 = Wp[2][a + 0], w21 = Wp[2][a + 1], w22 = Wp[2][a + 2];
            a2 = fmaf(s0, w20.x, a2); a2 = fmaf(c0, w20.y, a2);
            a2 = fmaf(s1, w21.x, a2); a2 = fmaf(c1, w21.y, a2);
            a2 = fmaf(s2, w22.x, a2); a2 = fmaf(c2, w22.y, a2);

            // double-angle: s' = 2sc, c' = c^2 - s^2
            if (f < 9) {
                float ts, tc;
                ts = s0 * c0; tc = fmaf(c0, c0, -(s0 * s0)); s0 = ts + ts; c0 = tc;
                ts = s1 * c1; tc = fmaf(c1, c1, -(s1 * s1)); s1 = ts + ts; c1 = tc;
                ts = s2 * c2; tc = fmaf(c2, c2, -(s2 * s2)); s2 = ts + ts; c2 = tc;
            }
        }

        out[3 * r + 0] = a0;
        out[3 * r + 1] = a1;
        out[3 * r + 2] = a2;
    }
}

extern "C" void kernel_launch(void* const* d_in, const int* in_sizes, int n_in,
                              void* d_out, int out_size)
{
    const float* X         = (const float*)d_in[0];
    const float* W         = (const float*)d_in[1];
    const int*   row_ids   = (const int*)d_in[2];
    const int*   voxel_ids = (const int*)d_in[3];
    float*       out       = (float*)d_out;

    const int n = in_sizes[0] / 3;               // N_POINTS
    const int nb = (n + 255) / 256;

    hist_kernel<<<((n + 3) / 4 + 255) / 256, 256>>>(voxel_ids, n);
    scan_kernel<<<1, NUM_VOXELS>>>(n);
    scatter_kernel<<<nb, 256>>>(X, row_ids, voxel_ids, n);
    voxel_main_kernel<<<NUM_VOXELS * 2, 256>>>(W, out);
}